// round 10
// baseline (speedup 1.0000x reference)
#include <cuda_runtime.h>
#include <cuda_fp16.h>
#include <cstdint>
#include <math.h>

#define M_TOTAL 32768
#define SEQ     8192
#define H       1024
#define NB      4
#define KBA     2048                 // bytes per A row (1024 fp16)
#define KBB     2048                 // bytes per B row (1024 fp16)
#define NCH     16                   // 16 K-chunks of 64 fp16 (128B)
#define STAGE_BYTES 49152            // 32KB A (256 rows) + 16KB B (128 rows)
#define SMEM_TOTAL (3*STAGE_BYTES)   // 144KB

// ---------------- scratch -----------------------------------------------
__device__ __half g_Ax[(size_t)M_TOTAL * H];     // x, fp16
__device__ __half g_Vp[(size_t)M_TOTAL * H];     // V', fp16
__device__ __half g_Qf[(size_t)M_TOTAL * H];     // elu(q)+1, fp16
__device__ __half g_Bqkv[(size_t)3072 * H];      // [Q rows | K/V interleaved rows]
__device__ __half g_Bo [(size_t)1024 * H];       // out weights
__device__ float  g_KV[NB * H];
__device__ float  g_Ksum[NB * H];

// ---------------- helpers ------------------------------------------------
__device__ __forceinline__ uint32_t smem_u32(const void* p) {
    uint32_t a;
    asm("{ .reg .u64 t; cvta.to.shared.u64 t, %1; cvt.u32.u64 %0, t; }" : "=r"(a) : "l"(p));
    return a;
}
__device__ __forceinline__ void cp16(uint32_t dst, const void* src) {
    asm volatile("cp.async.cg.shared.global [%0], [%1], 16;" :: "r"(dst), "l"(src));
}
__device__ __forceinline__ void cpcommit() {
    asm volatile("cp.async.commit_group;" ::: "memory");
}
template <int N> __device__ __forceinline__ void cpwait() {
    asm volatile("cp.async.wait_group %0;" :: "n"(N) : "memory");
}
__device__ __forceinline__ void ldmx4(uint32_t* r, uint32_t addr) {
    asm volatile("ldmatrix.sync.aligned.m8n8.x4.shared.b16 {%0,%1,%2,%3}, [%4];"
                 : "=r"(r[0]), "=r"(r[1]), "=r"(r[2]), "=r"(r[3]) : "r"(addr));
}
__device__ __forceinline__ void mma16816(float* d, const uint32_t* a, uint32_t b0, uint32_t b1) {
    asm volatile(
        "mma.sync.aligned.m16n8k16.row.col.f32.f16.f16.f32 "
        "{%0,%1,%2,%3}, {%4,%5,%6,%7}, {%8,%9}, {%0,%1,%2,%3};"
        : "+f"(d[0]), "+f"(d[1]), "+f"(d[2]), "+f"(d[3])
        : "r"(a[0]), "r"(a[1]), "r"(a[2]), "r"(a[3]), "r"(b0), "r"(b1));
}
__device__ __forceinline__ float elu1(float x) { return x > 0.f ? x + 1.f : __expf(x); }
__device__ __forceinline__ float fast_tanh(float x) {
    float y;
    asm("tanh.approx.f32 %0, %1;" : "=f"(y) : "f"(x));
    return y;
}
__device__ __forceinline__ float gelu(float v) {
    float t = 0.7978845608028654f * (v + 0.044715f * v * v * v);
    return 0.5f * v * (1.0f + fast_tanh(t));
}

// ---------------- small kernels ------------------------------------------
__global__ void zero_kernel() {
    int i = blockIdx.x * blockDim.x + threadIdx.x;
    if (i < NB * H) { g_KV[i] = 0.f; g_Ksum[i] = 0.f; }
}

// x fp32 -> fp16
__global__ __launch_bounds__(256) void conv_x_kernel(const float* __restrict__ x) {
    size_t idx = (size_t)blockIdx.x * 256 + threadIdx.x;
    size_t k = idx << 2;
    float4 v = *(const float4*)&x[k];
    __half2* p = (__half2*)&g_Ax[k];
    p[0] = {__float2half(v.x), __float2half(v.y)};
    p[1] = {__float2half(v.z), __float2half(v.w)};
}

// weights -> fp16 rows via tiled 64x64 smem transpose.
// B layout: rows 0-1023 = Q; rows 1024-3071 = K/V interleaved 64-blocks
// [32 K-ch | 32 matching V-ch]. Separate g_Bo for output weights.
__global__ __launch_bounds__(256) void conv_w_kernel(
    const float* __restrict__ wq, const float* __restrict__ wk,
    const float* __restrict__ wv, const float* __restrict__ wo) {
    __shared__ float s[64][65];
    const int tid = threadIdx.x;
    const int which = blockIdx.y;
    const int k0 = (blockIdx.x >> 4) * 64;
    const int h0 = (blockIdx.x & 15) * 64;
    const float* w = (which == 0) ? wq : (which == 1) ? wk : (which == 2) ? wv : wo;

    #pragma unroll
    for (int pass = 0; pass < 4; pass++) {
        int r = (tid >> 4) + pass * 16;
        int c4 = (tid & 15) << 2;
        float4 v = *(const float4*)&w[(size_t)(k0 + r) * H + h0 + c4];
        s[r][c4 + 0] = v.x; s[r][c4 + 1] = v.y;
        s[r][c4 + 2] = v.z; s[r][c4 + 3] = v.w;
    }
    __syncthreads();

    #pragma unroll
    for (int pass = 0; pass < 2; pass++) {
        int idx = pass * 256 + tid;
        int hh = idx >> 3;
        int seg = idx & 7;
        int h = h0 + hh;
        __half* row;
        if (which == 0)      row = &g_Bqkv[(size_t)h * H];
        else if (which == 1) row = &g_Bqkv[(size_t)(1024 + (h >> 5) * 64 + (h & 31)) * H];
        else if (which == 2) row = &g_Bqkv[(size_t)(1024 + (h >> 5) * 64 + 32 + (h & 31)) * H];
        else                 row = &g_Bo[(size_t)h * H];
        int kk = seg * 8;
        __half2 h4[4];
        #pragma unroll
        for (int i = 0; i < 4; i++)
            h4[i] = {__float2half(s[kk + 2 * i][hh]), __float2half(s[kk + 2 * i + 1][hh])};
        *(uint4*)&row[k0 + kk] = *(uint4*)h4;
    }
}

// V' = Qf*KV / (Qf*Ksum + 1e-6) -> fp16
__global__ __launch_bounds__(256) void vprime_kernel() {
    int m = blockIdx.x;
    int bn = m / SEQ;
    int hh = threadIdx.x * 4;
    const __half2* qp = (const __half2*)&g_Qf[(size_t)m * H + hh];
    __half2 q01 = qp[0], q23 = qp[1];
    float q[4] = {__half2float(q01.x), __half2float(q01.y),
                  __half2float(q23.x), __half2float(q23.y)};
    float4 kv = *(const float4*)&g_KV[bn * H + hh];
    float4 ks = *(const float4*)&g_Ksum[bn * H + hh];
    float a[4] = {kv.x, kv.y, kv.z, kv.w};
    float b[4] = {ks.x, ks.y, ks.z, ks.w};
    __half hi[4];
    #pragma unroll
    for (int i = 0; i < 4; i++)
        hi[i] = __float2half(q[i] * a[i] * (1.0f / (q[i] * b[i] + 1e-6f)));
    __half2* p = (__half2*)&g_Vp[(size_t)m * H + hh];
    p[0] = {hi[0], hi[1]}; p[1] = {hi[2], hi[3]};
}

// ---------------- HMMA GEMM ----------------------------------------------
// CTA tile 256x128, 256 threads (8 warps, grid 4Mx2N), warp tile 64x64,
// 3-stage pipe, fp16, K=1024, 1 CTA/SM (144KB smem).
// MODE 0: fused QKV-GEMM (N=3072). n0<1024: Q tile -> elu1 -> g_Qf.
//         n0>=1024: KV tile -> per-channel reduction.
// MODE 1: out-GEMM (N=1024) -> bias+gelu -> out.
template <int MODE>
__global__ __launch_bounds__(256, 1) void gemm_kernel(
    const float* __restrict__ b0p,
    const float* __restrict__ b1p,
    const float* __restrict__ b2p,
    float* __restrict__ outp)
{
    extern __shared__ __align__(1024) char smv[];
    const uint32_t sb = smem_u32(smv);
    const int tid = threadIdx.x;
    const int w = tid >> 5, l = tid & 31;

    const size_t m0 = (size_t)blockIdx.y * 256;
    const int n0 = blockIdx.x * 128;

    const __half* A = (MODE == 1) ? g_Vp : g_Ax;
    const __half* B = (MODE == 1) ? g_Bo : g_Bqkv;

    // cp.async: 256 threads; A: 256 rows x 8 segs (8/thr), B: 128 rows x 8 (4/thr)
    const char* Asrc = (const char*)A + (m0 + (tid >> 3)) * (size_t)KBA + ((tid & 7) << 4);
    const char* Bsrc = (const char*)B + ((size_t)(n0 + (tid >> 3))) * KBB + ((tid & 7) << 4);
    const uint32_t dst0 = ((tid >> 3) << 7) + ((((tid & 7) << 4)) ^ ((((tid >> 3) & 7)) << 4));

    auto load_chunk = [&](int ch, int s) {
        uint32_t sa = sb + s * STAGE_BYTES + dst0;
        uint32_t sbm = sa + 32768;
        const char* as = Asrc + (size_t)ch * 128;
        const char* bs = Bsrc + (size_t)ch * 128;
        #pragma unroll
        for (int j = 0; j < 8; j++) cp16(sa + (j << 12), as + j * (size_t)(32 * KBA));
        #pragma unroll
        for (int j = 0; j < 4; j++) cp16(sbm + (j << 12), bs + j * (size_t)(32 * KBB));
        cpcommit();
    };

    // warp/lane geometry: warp tile 64(M) x 64(N), warp grid 4x2
    const int wm = (w & 3) << 6;
    const int wn = (w >> 2) << 6;
    const uint32_t lx = (l & 7) << 4;
    const int arow = ((l >> 3) & 1) * 8 + (l & 7);
    const uint32_t ahb = (l >> 4) & 1;
    const int brow = ((l >> 4) & 1) * 8 + (l & 7);
    const uint32_t bhb = (l >> 3) & 1;

    float acc[128];
    #pragma unroll
    for (int i = 0; i < 128; i++) acc[i] = 0.f;

    load_chunk(0, 0);
    load_chunk(1, 1);

    #pragma unroll 1
    for (int c = 0; c < NCH; c++) {
        if (c < NCH - 2) cpwait<1>(); else cpwait<0>();
        __syncthreads();
        if (c + 2 < NCH) load_chunk(c + 2, (c + 2) % 3);

        const uint32_t stA = sb + (c % 3) * STAGE_BYTES;
        const uint32_t stB = stA + 32768;
        #pragma unroll
        for (int ks = 0; ks < 4; ks++) {
            const uint32_t koffA = (((uint32_t)ks << 5) | (ahb << 4)) ^ lx;
            const uint32_t koffB = (((uint32_t)ks << 5) | (bhb << 4)) ^ lx;
            uint32_t af[4][4];
            #pragma unroll
            for (int mt = 0; mt < 4; mt++)
                ldmx4(af[mt], stA + ((uint32_t)(wm + mt * 16 + arow) << 7) + koffA);
            uint32_t bf[4][4];
            #pragma unroll
            for (int j = 0; j < 4; j++)
                ldmx4(bf[j], stB + ((uint32_t)(wn + j * 16 + brow) << 7) + koffB);
            #pragma unroll
            for (int mt = 0; mt < 4; mt++)
                #pragma unroll
                for (int nt = 0; nt < 8; nt++)
                    mma16816(&acc[(mt * 8 + nt) * 4], af[mt],
                             bf[nt >> 1][(nt & 1) * 2], bf[nt >> 1][(nt & 1) * 2 + 1]);
        }
    }
    __syncthreads();   // retire last-stage reads before smem reuse

    // ------------- epilogue -------------
    const int cl = (l & 3) << 1;

    if (MODE == 0 && n0 >= 1024) {
        // KV tile: warp's 64 cols = [32 K-ch | 32 matching V-ch]; pair nt <-> nt+4
        const int hbase = ((n0 - 1024) >> 6) * 32;
        const int hw = hbase + (wn >> 1);
        const int bn = (int)(m0 / SEQ);
        float pkv[8], pks[8];
        #pragma unroll
        for (int i = 0; i < 8; i++) { pkv[i] = 0.f; pks[i] = 0.f; }
        #pragma unroll
        for (int mt = 0; mt < 4; mt++)
            #pragma unroll
            for (int nt = 0; nt < 4; nt++)
                #pragma unroll
                for (int i = 0; i < 4; i++) {
                    int hl = nt * 8 + cl + (i & 1);
                    float kf = elu1(acc[(mt * 8 + nt) * 4 + i] + __ldg(&b1p[hw + hl]));
                    float vv = acc[(mt * 8 + nt + 4) * 4 + i] + __ldg(&b2p[hw + hl]);
                    int e = nt * 2 + (i & 1);
                    pkv[e] += kf * vv;
                    pks[e] += kf;
                }
        #pragma unroll
        for (int off = 16; off >= 4; off >>= 1)
            #pragma unroll
            for (int e = 0; e < 8; e++) {
                pkv[e] += __shfl_down_sync(0xffffffffu, pkv[e], off);
                pks[e] += __shfl_down_sync(0xffffffffu, pks[e], off);
            }
        float* redkv = (float*)smv;          // [8 warps][32]
        float* redks = redkv + 8 * 32;
        if (l < 4) {
            #pragma unroll
            for (int e = 0; e < 8; e++) {
                int hl = (e >> 1) * 8 + l * 2 + (e & 1);
                redkv[w * 32 + hl] = pkv[e];
                redks[w * 32 + hl] = pks[e];
            }
        }
        __syncthreads();
        if (tid < 128) {
            int cc = tid & 63;
            int w0 = (cc >> 5) * 4;          // warps 0-3: cols 0-63; warps 4-7: 64-127
            float* src = (tid < 64) ? redkv : redks;
            float s = 0.f;
            #pragma unroll
            for (int j = 0; j < 4; j++) s += src[(w0 + j) * 32 + (cc & 31)];
            float* dst = (tid < 64) ? &g_KV[bn * H + hbase + cc]
                                    : &g_Ksum[bn * H + hbase + cc];
            atomicAdd(dst, s);
        }
    } else {
        // Q tile (MODE 0, elu1 -> g_Qf fp16) or out tile (MODE 1, gelu -> fp32)
        float* ep = (float*)smv;             // [256][132] = 135KB, fits in 144KB
        #pragma unroll
        for (int mt = 0; mt < 4; mt++)
            #pragma unroll
            for (int nt = 0; nt < 8; nt++) {
                int c0 = wn + nt * 8 + cl;
                float bb0 = __ldg(&b0p[n0 + c0]);
                float bb1 = __ldg(&b0p[n0 + c0 + 1]);
                int r0 = wm + mt * 16 + (l >> 2);
                float v0 = acc[(mt * 8 + nt) * 4 + 0] + bb0;
                float v1 = acc[(mt * 8 + nt) * 4 + 1] + bb1;
                float v2 = acc[(mt * 8 + nt) * 4 + 2] + bb0;
                float v3 = acc[(mt * 8 + nt) * 4 + 3] + bb1;
                if (MODE == 0) { v0 = elu1(v0); v1 = elu1(v1); v2 = elu1(v2); v3 = elu1(v3); }
                else           { v0 = gelu(v0); v1 = gelu(v1); v2 = gelu(v2); v3 = gelu(v3); }
                ep[r0 * 132 + c0] = v0;        ep[r0 * 132 + c0 + 1] = v1;
                ep[(r0 + 8) * 132 + c0] = v2;  ep[(r0 + 8) * 132 + c0 + 1] = v3;
            }
        __syncthreads();
        if (MODE == 0) {
            #pragma unroll 8
            for (int i = 0; i < 128; i++) {
                int idx = i * 256 + tid;
                int rr = idx >> 7, cc = idx & 127;
                g_Qf[(m0 + rr) * H + n0 + cc] = __float2half(ep[rr * 132 + cc]);
            }
        } else {
            #pragma unroll 8
            for (int i = 0; i < 128; i++) {
                int idx = i * 256 + tid;
                int rr = idx >> 7, cc = idx & 127;
                outp[(m0 + rr) * H + n0 + cc] = ep[rr * 132 + cc];
            }
        }
    }
}

// ---------------- launch --------------------------------------------------
extern "C" void kernel_launch(void* const* d_in, const int* in_sizes, int n_in,
                              void* d_out, int out_size) {
    const float* x  = (const float*)d_in[0];
    const float* wq = (const float*)d_in[1];
    const float* bq = (const float*)d_in[2];
    const float* wk = (const float*)d_in[3];
    const float* bk = (const float*)d_in[4];
    const float* wv = (const float*)d_in[5];
    const float* bv = (const float*)d_in[6];
    const float* wo = (const float*)d_in[7];
    const float* bo = (const float*)d_in[8];
    float* out = (float*)d_out;

    cudaFuncSetAttribute(gemm_kernel<0>, cudaFuncAttributeMaxDynamicSharedMemorySize, SMEM_TOTAL);
    cudaFuncSetAttribute(gemm_kernel<1>, cudaFuncAttributeMaxDynamicSharedMemorySize, SMEM_TOTAL);

    zero_kernel<<<(NB * H + 255) / 256, 256>>>();
    conv_x_kernel<<<M_TOTAL * H / 1024, 256>>>(x);
    conv_w_kernel<<<dim3(256, 4), 256>>>(wq, wk, wv, wo);

    gemm_kernel<0><<<dim3(24, M_TOTAL / 256), 256, SMEM_TOTAL>>>(bq, bk, bv, nullptr);
    vprime_kernel<<<M_TOTAL, 256>>>();
    gemm_kernel<1><<<dim3(8, M_TOTAL / 256), 256, SMEM_TOTAL>>>(bo, nullptr, nullptr, out);
}

// round 11
// speedup vs baseline: 1.1563x; 1.1563x over previous
#include <cuda_runtime.h>
#include <cuda_fp16.h>
#include <cstdint>
#include <math.h>

#define M_TOTAL 32768
#define SEQ     8192
#define H       1024
#define NB      4
#define KBA     2048                 // bytes per A row (1024 fp16)
#define KBB     2048                 // bytes per B row (1024 fp16)
#define NCH     16                   // 16 K-chunks of 64 fp16 (128B)
#define STAGE_BYTES 32768            // 16KB A + 16KB B
#define SMEM_TOTAL (3*STAGE_BYTES)   // 96KB

// ---------------- scratch -----------------------------------------------
__device__ __half g_Ax[(size_t)M_TOTAL * H];     // x, fp16
__device__ __half g_Vp[(size_t)M_TOTAL * H];     // V', fp16
__device__ __half g_Qf[(size_t)M_TOTAL * H];     // elu(q)+1, fp16
__device__ __half g_Bqkv[(size_t)3072 * H];      // [Q rows | K/V interleaved rows]
__device__ __half g_Bo [(size_t)1024 * H];       // out weights
__device__ float  g_KV[NB * H];
__device__ float  g_Ksum[NB * H];

// ---------------- helpers ------------------------------------------------
__device__ __forceinline__ uint32_t smem_u32(const void* p) {
    uint32_t a;
    asm("{ .reg .u64 t; cvta.to.shared.u64 t, %1; cvt.u32.u64 %0, t; }" : "=r"(a) : "l"(p));
    return a;
}
__device__ __forceinline__ void cp16(uint32_t dst, const void* src) {
    asm volatile("cp.async.cg.shared.global [%0], [%1], 16;" :: "r"(dst), "l"(src));
}
__device__ __forceinline__ void cpcommit() {
    asm volatile("cp.async.commit_group;" ::: "memory");
}
template <int N> __device__ __forceinline__ void cpwait() {
    asm volatile("cp.async.wait_group %0;" :: "n"(N) : "memory");
}
__device__ __forceinline__ void ldmx4(uint32_t* r, uint32_t addr) {
    asm volatile("ldmatrix.sync.aligned.m8n8.x4.shared.b16 {%0,%1,%2,%3}, [%4];"
                 : "=r"(r[0]), "=r"(r[1]), "=r"(r[2]), "=r"(r[3]) : "r"(addr));
}
__device__ __forceinline__ void mma16816(float* d, const uint32_t* a, uint32_t b0, uint32_t b1) {
    asm volatile(
        "mma.sync.aligned.m16n8k16.row.col.f32.f16.f16.f32 "
        "{%0,%1,%2,%3}, {%4,%5,%6,%7}, {%8,%9}, {%0,%1,%2,%3};"
        : "+f"(d[0]), "+f"(d[1]), "+f"(d[2]), "+f"(d[3])
        : "r"(a[0]), "r"(a[1]), "r"(a[2]), "r"(a[3]), "r"(b0), "r"(b1));
}
__device__ __forceinline__ float elu1(float x) { return x > 0.f ? x + 1.f : __expf(x); }
__device__ __forceinline__ float fast_tanh(float x) {
    float y;
    asm("tanh.approx.f32 %0, %1;" : "=f"(y) : "f"(x));
    return y;
}
__device__ __forceinline__ float gelu(float v) {
    float t = 0.7978845608028654f * (v + 0.044715f * v * v * v);
    return 0.5f * v * (1.0f + fast_tanh(t));
}

// ---------------- small kernels ------------------------------------------
__global__ void zero_kernel() {
    int i = blockIdx.x * blockDim.x + threadIdx.x;
    if (i < NB * H) { g_KV[i] = 0.f; g_Ksum[i] = 0.f; }
}

// x fp32 -> fp16
__global__ __launch_bounds__(256) void conv_x_kernel(const float* __restrict__ x) {
    size_t idx = (size_t)blockIdx.x * 256 + threadIdx.x;
    size_t k = idx << 2;
    float4 v = *(const float4*)&x[k];
    __half2* p = (__half2*)&g_Ax[k];
    p[0] = {__float2half(v.x), __float2half(v.y)};
    p[1] = {__float2half(v.z), __float2half(v.w)};
}

// weights -> fp16 rows via tiled 64x64 smem transpose.
// B layout: rows 0-1023 = Q; rows 1024-3071 = K/V interleaved 64-blocks
// [32 K-ch | 32 matching V-ch]. Separate g_Bo for output weights.
__global__ __launch_bounds__(256) void conv_w_kernel(
    const float* __restrict__ wq, const float* __restrict__ wk,
    const float* __restrict__ wv, const float* __restrict__ wo) {
    __shared__ float s[64][65];
    const int tid = threadIdx.x;
    const int which = blockIdx.y;
    const int k0 = (blockIdx.x >> 4) * 64;
    const int h0 = (blockIdx.x & 15) * 64;
    const float* w = (which == 0) ? wq : (which == 1) ? wk : (which == 2) ? wv : wo;

    #pragma unroll
    for (int pass = 0; pass < 4; pass++) {
        int r = (tid >> 4) + pass * 16;
        int c4 = (tid & 15) << 2;
        float4 v = *(const float4*)&w[(size_t)(k0 + r) * H + h0 + c4];
        s[r][c4 + 0] = v.x; s[r][c4 + 1] = v.y;
        s[r][c4 + 2] = v.z; s[r][c4 + 3] = v.w;
    }
    __syncthreads();

    #pragma unroll
    for (int pass = 0; pass < 2; pass++) {
        int idx = pass * 256 + tid;
        int hh = idx >> 3;
        int seg = idx & 7;
        int h = h0 + hh;
        __half* row;
        if (which == 0)      row = &g_Bqkv[(size_t)h * H];
        else if (which == 1) row = &g_Bqkv[(size_t)(1024 + (h >> 5) * 64 + (h & 31)) * H];
        else if (which == 2) row = &g_Bqkv[(size_t)(1024 + (h >> 5) * 64 + 32 + (h & 31)) * H];
        else                 row = &g_Bo[(size_t)h * H];
        int kk = seg * 8;
        __half2 h4[4];
        #pragma unroll
        for (int i = 0; i < 4; i++)
            h4[i] = {__float2half(s[kk + 2 * i][hh]), __float2half(s[kk + 2 * i + 1][hh])};
        *(uint4*)&row[k0 + kk] = *(uint4*)h4;
    }
}

// V' = Qf*KV / (Qf*Ksum + 1e-6) -> fp16
__global__ __launch_bounds__(256) void vprime_kernel() {
    int m = blockIdx.x;
    int bn = m / SEQ;
    int hh = threadIdx.x * 4;
    const __half2* qp = (const __half2*)&g_Qf[(size_t)m * H + hh];
    __half2 q01 = qp[0], q23 = qp[1];
    float q[4] = {__half2float(q01.x), __half2float(q01.y),
                  __half2float(q23.x), __half2float(q23.y)};
    float4 kv = *(const float4*)&g_KV[bn * H + hh];
    float4 ks = *(const float4*)&g_Ksum[bn * H + hh];
    float a[4] = {kv.x, kv.y, kv.z, kv.w};
    float b[4] = {ks.x, ks.y, ks.z, ks.w};
    __half hi[4];
    #pragma unroll
    for (int i = 0; i < 4; i++)
        hi[i] = __float2half(q[i] * a[i] * (1.0f / (q[i] * b[i] + 1e-6f)));
    __half2* p = (__half2*)&g_Vp[(size_t)m * H + hh];
    p[0] = {hi[0], hi[1]}; p[1] = {hi[2], hi[3]};
}

// ---------------- HMMA GEMM ----------------------------------------------
// CTA tile 128x128, 128 threads (4 warps), warp tile 64x64, 3-stage pipe,
// 2 CTA/SM, intra-chunk fragment double-buffering.
// MODE 0: fused QKV-GEMM (N=3072). n0<1024: Q tile -> elu1 -> g_Qf.
//         n0>=1024: KV tile -> per-channel reduction.
// MODE 1: out-GEMM (N=1024) -> bias+gelu -> out.
template <int MODE>
__global__ __launch_bounds__(128, 2) void gemm_kernel(
    const float* __restrict__ b0p,
    const float* __restrict__ b1p,
    const float* __restrict__ b2p,
    float* __restrict__ outp)
{
    extern __shared__ __align__(1024) char smv[];
    const uint32_t sb = smem_u32(smv);
    const int tid = threadIdx.x;
    const int w = tid >> 5, l = tid & 31;

    const size_t m0 = (size_t)blockIdx.y * 128;
    const int n0 = blockIdx.x * 128;

    const __half* A = (MODE == 1) ? g_Vp : g_Ax;
    const __half* B = (MODE == 1) ? g_Bo : g_Bqkv;

    // cp.async: 128 threads cover 128 rows x 128B for A and B each
    const char* Asrc = (const char*)A + (m0 + (tid >> 3)) * (size_t)KBA + ((tid & 7) << 4);
    const char* Bsrc = (const char*)B + ((size_t)(n0 + (tid >> 3))) * KBB + ((tid & 7) << 4);
    const uint32_t dst0 = ((tid >> 3) << 7) + ((((tid & 7) << 4)) ^ ((((tid >> 3) & 7)) << 4));

    auto load_chunk = [&](int ch, int s) {
        uint32_t sa = sb + s * STAGE_BYTES + dst0;
        uint32_t sbm = sa + 16384;
        const char* as = Asrc + (size_t)ch * 128;
        const char* bs = Bsrc + (size_t)ch * 128;
        #pragma unroll
        for (int j = 0; j < 8; j++) cp16(sa + (j << 11), as + j * (size_t)(16 * KBA));
        #pragma unroll
        for (int j = 0; j < 8; j++) cp16(sbm + (j << 11), bs + j * (size_t)(16 * KBB));
        cpcommit();
    };

    // warp/lane geometry: warp tile 64(M) x 64(N), warp grid 2x2
    const int wm = (w & 1) << 6;
    const int wn = (w >> 1) << 6;
    const uint32_t lx = (l & 7) << 4;
    const int arow = ((l >> 3) & 1) * 8 + (l & 7);
    const uint32_t ahb = (l >> 4) & 1;
    const int brow = ((l >> 4) & 1) * 8 + (l & 7);
    const uint32_t bhb = (l >> 3) & 1;

    float acc[128];
    #pragma unroll
    for (int i = 0; i < 128; i++) acc[i] = 0.f;

    uint32_t af[2][4][4], bf[2][4][4];

    load_chunk(0, 0);
    load_chunk(1, 1);

    #pragma unroll 1
    for (int c = 0; c < NCH; c++) {
        if (c < NCH - 2) cpwait<1>(); else cpwait<0>();
        __syncthreads();
        if (c + 2 < NCH) load_chunk(c + 2, (c + 2) % 3);

        const uint32_t stA = sb + (c % 3) * STAGE_BYTES;
        const uint32_t stB = stA + 16384;

        // fragment loader for one ks into buffer pb
        auto load_frags = [&](int ks, int pb) {
            const uint32_t koffA = (((uint32_t)ks << 5) | (ahb << 4)) ^ lx;
            const uint32_t koffB = (((uint32_t)ks << 5) | (bhb << 4)) ^ lx;
            #pragma unroll
            for (int mt = 0; mt < 4; mt++)
                ldmx4(af[pb][mt], stA + ((uint32_t)(wm + mt * 16 + arow) << 7) + koffA);
            #pragma unroll
            for (int j = 0; j < 4; j++)
                ldmx4(bf[pb][j], stB + ((uint32_t)(wn + j * 16 + brow) << 7) + koffB);
        };

        load_frags(0, 0);
        #pragma unroll
        for (int ks = 0; ks < 4; ks++) {
            const int cur = ks & 1;
            if (ks < 3) load_frags(ks + 1, cur ^ 1);
            #pragma unroll
            for (int mt = 0; mt < 4; mt++)
                #pragma unroll
                for (int nt = 0; nt < 8; nt++)
                    mma16816(&acc[(mt * 8 + nt) * 4], af[cur][mt],
                             bf[cur][nt >> 1][(nt & 1) * 2], bf[cur][nt >> 1][(nt & 1) * 2 + 1]);
        }
    }
    __syncthreads();   // retire last-stage reads before smem reuse

    // ------------- epilogue -------------
    const int cl = (l & 3) << 1;

    if (MODE == 0 && n0 >= 1024) {
        // KV tile: warp's 64 cols = [32 K-ch | 32 matching V-ch]; pair nt <-> nt+4
        const int hbase = ((n0 - 1024) >> 6) * 32;
        const int hw = hbase + (wn >> 1);
        const int bn = (int)(m0 / SEQ);
        float pkv[8], pks[8];
        #pragma unroll
        for (int i = 0; i < 8; i++) { pkv[i] = 0.f; pks[i] = 0.f; }
        #pragma unroll
        for (int mt = 0; mt < 4; mt++)
            #pragma unroll
            for (int nt = 0; nt < 4; nt++)
                #pragma unroll
                for (int i = 0; i < 4; i++) {
                    int hl = nt * 8 + cl + (i & 1);
                    float kf = elu1(acc[(mt * 8 + nt) * 4 + i] + __ldg(&b1p[hw + hl]));
                    float vv = acc[(mt * 8 + nt + 4) * 4 + i] + __ldg(&b2p[hw + hl]);
                    int e = nt * 2 + (i & 1);
                    pkv[e] += kf * vv;
                    pks[e] += kf;
                }
        #pragma unroll
        for (int off = 16; off >= 4; off >>= 1)
            #pragma unroll
            for (int e = 0; e < 8; e++) {
                pkv[e] += __shfl_down_sync(0xffffffffu, pkv[e], off);
                pks[e] += __shfl_down_sync(0xffffffffu, pks[e], off);
            }
        float* redkv = (float*)smv;          // [4 warps][32]
        float* redks = redkv + 4 * 32;
        if (l < 4) {
            #pragma unroll
            for (int e = 0; e < 8; e++) {
                int hl = (e >> 1) * 8 + l * 2 + (e & 1);
                redkv[w * 32 + hl] = pkv[e];
                redks[w * 32 + hl] = pks[e];
            }
        }
        __syncthreads();
        {
            int cc = tid & 63;
            int w0 = (cc >> 5) * 2;          // warps {0,1} cols 0-63; {2,3} cols 64-127
            float* src = (tid < 64) ? redkv : redks;
            float s = src[w0 * 32 + (cc & 31)] + src[(w0 + 1) * 32 + (cc & 31)];
            float* dst = (tid < 64) ? &g_KV[bn * H + hbase + cc]
                                    : &g_Ksum[bn * H + hbase + cc];
            atomicAdd(dst, s);
        }
    } else {
        // Q tile (MODE 0, elu1 -> g_Qf fp16) or out tile (MODE 1, gelu -> fp32)
        float* ep = (float*)smv;             // [128][132]
        #pragma unroll
        for (int mt = 0; mt < 4; mt++)
            #pragma unroll
            for (int nt = 0; nt < 8; nt++) {
                int c0 = wn + nt * 8 + cl;
                float bb0 = __ldg(&b0p[n0 + c0]);
                float bb1 = __ldg(&b0p[n0 + c0 + 1]);
                int r0 = wm + mt * 16 + (l >> 2);
                float v0 = acc[(mt * 8 + nt) * 4 + 0] + bb0;
                float v1 = acc[(mt * 8 + nt) * 4 + 1] + bb1;
                float v2 = acc[(mt * 8 + nt) * 4 + 2] + bb0;
                float v3 = acc[(mt * 8 + nt) * 4 + 3] + bb1;
                if (MODE == 0) { v0 = elu1(v0); v1 = elu1(v1); v2 = elu1(v2); v3 = elu1(v3); }
                else           { v0 = gelu(v0); v1 = gelu(v1); v2 = gelu(v2); v3 = gelu(v3); }
                ep[r0 * 132 + c0] = v0;        ep[r0 * 132 + c0 + 1] = v1;
                ep[(r0 + 8) * 132 + c0] = v2;  ep[(r0 + 8) * 132 + c0 + 1] = v3;
            }
        __syncthreads();
        if (MODE == 0) {
            #pragma unroll 8
            for (int i = 0; i < 128; i++) {
                int idx = i * 128 + tid;
                int rr = idx >> 7, cc = idx & 127;
                g_Qf[(m0 + rr) * H + n0 + cc] = __float2half(ep[rr * 132 + cc]);
            }
        } else {
            #pragma unroll 8
            for (int i = 0; i < 128; i++) {
                int idx = i * 128 + tid;
                int rr = idx >> 7, cc = idx & 127;
                outp[(m0 + rr) * H + n0 + cc] = ep[rr * 132 + cc];
            }
        }
    }
}

// ---------------- launch --------------------------------------------------
extern "C" void kernel_launch(void* const* d_in, const int* in_sizes, int n_in,
                              void* d_out, int out_size) {
    const float* x  = (const float*)d_in[0];
    const float* wq = (const float*)d_in[1];
    const float* bq = (const float*)d_in[2];
    const float* wk = (const float*)d_in[3];
    const float* bk = (const float*)d_in[4];
    const float* wv = (const float*)d_in[5];
    const float* bv = (const float*)d_in[6];
    const float* wo = (const float*)d_in[7];
    const float* bo = (const float*)d_in[8];
    float* out = (float*)d_out;

    cudaFuncSetAttribute(gemm_kernel<0>, cudaFuncAttributeMaxDynamicSharedMemorySize, SMEM_TOTAL);
    cudaFuncSetAttribute(gemm_kernel<1>, cudaFuncAttributeMaxDynamicSharedMemorySize, SMEM_TOTAL);

    zero_kernel<<<(NB * H + 255) / 256, 256>>>();
    conv_x_kernel<<<M_TOTAL * H / 1024, 256>>>(x);
    conv_w_kernel<<<dim3(256, 4), 256>>>(wq, wk, wv, wo);

    gemm_kernel<0><<<dim3(24, M_TOTAL / 128), 128, SMEM_TOTAL>>>(bq, bk, bv, nullptr);
    vprime_kernel<<<M_TOTAL, 256>>>();
    gemm_kernel<1><<<dim3(8, M_TOTAL / 128), 128, SMEM_TOTAL>>>(bo, nullptr, nullptr, out);
}

// round 12
// speedup vs baseline: 1.2149x; 1.0506x over previous
#include <cuda_runtime.h>
#include <cuda_fp16.h>
#include <cstdint>
#include <math.h>

#define M_TOTAL 32768
#define SEQ     8192
#define H       1024
#define NB      4
#define KBA     2048                 // bytes per A row (1024 fp16)
#define KBB     2048                 // bytes per B row (1024 fp16)
#define NCH     16                   // 16 K-chunks of 64 fp16 (128B)
#define STAGE_BYTES 32768            // 16KB A + 16KB B
#define SMEM_TOTAL (3*STAGE_BYTES)   // 96KB

// ---------------- scratch -----------------------------------------------
__device__ __half g_Ax[(size_t)M_TOTAL * H];     // x, fp16
__device__ __half g_Vp[(size_t)M_TOTAL * H];     // V', fp16
__device__ __half g_Qf[(size_t)M_TOTAL * H];     // elu(q)+1, fp16
__device__ __half g_Bqkv[(size_t)3072 * H];      // [Q rows | K/V interleaved rows]
__device__ __half g_Bo [(size_t)1024 * H];       // out weights
__device__ float  g_KV[NB * H];
__device__ float  g_Ksum[NB * H];

// ---------------- helpers ------------------------------------------------
__device__ __forceinline__ uint32_t smem_u32(const void* p) {
    uint32_t a;
    asm("{ .reg .u64 t; cvta.to.shared.u64 t, %1; cvt.u32.u64 %0, t; }" : "=r"(a) : "l"(p));
    return a;
}
__device__ __forceinline__ void cp16(uint32_t dst, const void* src) {
    asm volatile("cp.async.cg.shared.global [%0], [%1], 16;" :: "r"(dst), "l"(src));
}
__device__ __forceinline__ void cpcommit() {
    asm volatile("cp.async.commit_group;" ::: "memory");
}
template <int N> __device__ __forceinline__ void cpwait() {
    asm volatile("cp.async.wait_group %0;" :: "n"(N) : "memory");
}
__device__ __forceinline__ void ldmx4(uint32_t* r, uint32_t addr) {
    asm volatile("ldmatrix.sync.aligned.m8n8.x4.shared.b16 {%0,%1,%2,%3}, [%4];"
                 : "=r"(r[0]), "=r"(r[1]), "=r"(r[2]), "=r"(r[3]) : "r"(addr));
}
__device__ __forceinline__ void mma16816(float* d, const uint32_t* a, uint32_t b0, uint32_t b1) {
    asm volatile(
        "mma.sync.aligned.m16n8k16.row.col.f32.f16.f16.f32 "
        "{%0,%1,%2,%3}, {%4,%5,%6,%7}, {%8,%9}, {%0,%1,%2,%3};"
        : "+f"(d[0]), "+f"(d[1]), "+f"(d[2]), "+f"(d[3])
        : "r"(a[0]), "r"(a[1]), "r"(a[2]), "r"(a[3]), "r"(b0), "r"(b1));
}
__device__ __forceinline__ float elu1(float x) { return x > 0.f ? x + 1.f : __expf(x); }
__device__ __forceinline__ float fast_tanh(float x) {
    float y;
    asm("tanh.approx.f32 %0, %1;" : "=f"(y) : "f"(x));
    return y;
}
__device__ __forceinline__ float gelu(float v) {
    float t = 0.7978845608028654f * (v + 0.044715f * v * v * v);
    return 0.5f * v * (1.0f + fast_tanh(t));
}

// ---------------- small kernels ------------------------------------------
// x fp32 -> fp16 (+ first 16 blocks zero the reduction buffers)
__global__ __launch_bounds__(256) void conv_x_kernel(const float* __restrict__ x) {
    if (blockIdx.x < 16) {
        int i = blockIdx.x * 256 + threadIdx.x;
        g_KV[i] = 0.f;
        g_Ksum[i] = 0.f;
    }
    size_t idx = (size_t)blockIdx.x * 256 + threadIdx.x;
    size_t k = idx << 2;
    float4 v = *(const float4*)&x[k];
    __half2* p = (__half2*)&g_Ax[k];
    p[0] = {__float2half(v.x), __float2half(v.y)};
    p[1] = {__float2half(v.z), __float2half(v.w)};
}

// weights -> fp16 rows via tiled 64x64 smem transpose.
// B layout: rows 0-1023 = Q; rows 1024-3071 = K/V interleaved 64-blocks
// [32 K-ch | 32 matching V-ch]. Separate g_Bo for output weights.
__global__ __launch_bounds__(256) void conv_w_kernel(
    const float* __restrict__ wq, const float* __restrict__ wk,
    const float* __restrict__ wv, const float* __restrict__ wo) {
    __shared__ float s[64][65];
    const int tid = threadIdx.x;
    const int which = blockIdx.y;
    const int k0 = (blockIdx.x >> 4) * 64;
    const int h0 = (blockIdx.x & 15) * 64;
    const float* w = (which == 0) ? wq : (which == 1) ? wk : (which == 2) ? wv : wo;

    #pragma unroll
    for (int pass = 0; pass < 4; pass++) {
        int r = (tid >> 4) + pass * 16;
        int c4 = (tid & 15) << 2;
        float4 v = *(const float4*)&w[(size_t)(k0 + r) * H + h0 + c4];
        s[r][c4 + 0] = v.x; s[r][c4 + 1] = v.y;
        s[r][c4 + 2] = v.z; s[r][c4 + 3] = v.w;
    }
    __syncthreads();

    #pragma unroll
    for (int pass = 0; pass < 2; pass++) {
        int idx = pass * 256 + tid;
        int hh = idx >> 3;
        int seg = idx & 7;
        int h = h0 + hh;
        __half* row;
        if (which == 0)      row = &g_Bqkv[(size_t)h * H];
        else if (which == 1) row = &g_Bqkv[(size_t)(1024 + (h >> 5) * 64 + (h & 31)) * H];
        else if (which == 2) row = &g_Bqkv[(size_t)(1024 + (h >> 5) * 64 + 32 + (h & 31)) * H];
        else                 row = &g_Bo[(size_t)h * H];
        int kk = seg * 8;
        __half2 h4[4];
        #pragma unroll
        for (int i = 0; i < 4; i++)
            h4[i] = {__float2half(s[kk + 2 * i][hh]), __float2half(s[kk + 2 * i + 1][hh])};
        *(uint4*)&row[k0 + kk] = *(uint4*)h4;
    }
}

// V' = Qf*KV / (Qf*Ksum + 1e-6) -> fp16
__global__ __launch_bounds__(256) void vprime_kernel() {
    int m = blockIdx.x;
    int bn = m / SEQ;
    int hh = threadIdx.x * 4;
    const __half2* qp = (const __half2*)&g_Qf[(size_t)m * H + hh];
    __half2 q01 = qp[0], q23 = qp[1];
    float q[4] = {__half2float(q01.x), __half2float(q01.y),
                  __half2float(q23.x), __half2float(q23.y)};
    float4 kv = *(const float4*)&g_KV[bn * H + hh];
    float4 ks = *(const float4*)&g_Ksum[bn * H + hh];
    float a[4] = {kv.x, kv.y, kv.z, kv.w};
    float b[4] = {ks.x, ks.y, ks.z, ks.w};
    __half hi[4];
    #pragma unroll
    for (int i = 0; i < 4; i++)
        hi[i] = __float2half(q[i] * a[i] * (1.0f / (q[i] * b[i] + 1e-6f)));
    __half2* p = (__half2*)&g_Vp[(size_t)m * H + hh];
    p[0] = {hi[0], hi[1]}; p[1] = {hi[2], hi[3]};
}

// ---------------- HMMA GEMM ----------------------------------------------
// CTA tile 128x128, 128 threads (4 warps), warp tile 64x64, 3-stage pipe,
// 2 CTA/SM. Producer cp.async issues spread across the 4 ks iterations.
// MODE 0: fused QKV-GEMM (N=3072). n0<1024: Q tile -> elu1 -> g_Qf.
//         n0>=1024: KV tile -> per-channel reduction.
// MODE 1: out-GEMM (N=1024) -> bias+gelu -> out.
template <int MODE>
__global__ __launch_bounds__(128, 2) void gemm_kernel(
    const float* __restrict__ b0p,
    const float* __restrict__ b1p,
    const float* __restrict__ b2p,
    float* __restrict__ outp)
{
    extern __shared__ __align__(1024) char smv[];
    const uint32_t sb = smem_u32(smv);
    const int tid = threadIdx.x;
    const int w = tid >> 5, l = tid & 31;

    const size_t m0 = (size_t)blockIdx.y * 128;
    const int n0 = blockIdx.x * 128;

    const __half* A = (MODE == 1) ? g_Vp : g_Ax;
    const __half* B = (MODE == 1) ? g_Bo : g_Bqkv;

    // cp.async: 128 threads cover 128 rows x 128B for A and B each
    const char* Asrc = (const char*)A + (m0 + (tid >> 3)) * (size_t)KBA + ((tid & 7) << 4);
    const char* Bsrc = (const char*)B + ((size_t)(n0 + (tid >> 3))) * KBB + ((tid & 7) << 4);
    const uint32_t dst0 = ((tid >> 3) << 7) + ((((tid & 7) << 4)) ^ ((((tid >> 3) & 7)) << 4));

    auto load_chunk = [&](int ch, int s) {
        uint32_t sa = sb + s * STAGE_BYTES + dst0;
        uint32_t sbm = sa + 16384;
        const char* as = Asrc + (size_t)ch * 128;
        const char* bs = Bsrc + (size_t)ch * 128;
        #pragma unroll
        for (int j = 0; j < 8; j++) cp16(sa + (j << 11), as + j * (size_t)(16 * KBA));
        #pragma unroll
        for (int j = 0; j < 8; j++) cp16(sbm + (j << 11), bs + j * (size_t)(16 * KBB));
        cpcommit();
    };

    // quarter of a chunk load (2 A rows-groups + 2 B rows-groups per thread)
    auto load_quarter = [&](int ch, int s, int q) {
        uint32_t sa = sb + s * STAGE_BYTES + dst0;
        uint32_t sbm = sa + 16384;
        const char* as = Asrc + (size_t)ch * 128;
        const char* bs = Bsrc + (size_t)ch * 128;
        #pragma unroll
        for (int j = 2 * q; j < 2 * q + 2; j++) {
            cp16(sa + (j << 11), as + j * (size_t)(16 * KBA));
            cp16(sbm + (j << 11), bs + j * (size_t)(16 * KBB));
        }
    };

    // warp/lane geometry: warp tile 64(M) x 64(N), warp grid 2x2
    const int wm = (w & 1) << 6;
    const int wn = (w >> 1) << 6;
    const uint32_t lx = (l & 7) << 4;
    const int arow = ((l >> 3) & 1) * 8 + (l & 7);
    const uint32_t ahb = (l >> 4) & 1;
    const int brow = ((l >> 4) & 1) * 8 + (l & 7);
    const uint32_t bhb = (l >> 3) & 1;

    float acc[128];
    #pragma unroll
    for (int i = 0; i < 128; i++) acc[i] = 0.f;

    uint32_t af[2][4][4], bf[2][4][4];

    load_chunk(0, 0);
    load_chunk(1, 1);

    #pragma unroll 1
    for (int c = 0; c < NCH; c++) {
        if (c < NCH - 2) cpwait<1>(); else cpwait<0>();
        __syncthreads();

        const uint32_t stA = sb + (c % 3) * STAGE_BYTES;
        const uint32_t stB = stA + 16384;
        const bool pf = (c + 2 < NCH);
        const int ps = (c + 2) % 3;

        auto load_frags = [&](int ks, int pb) {
            const uint32_t koffA = (((uint32_t)ks << 5) | (ahb << 4)) ^ lx;
            const uint32_t koffB = (((uint32_t)ks << 5) | (bhb << 4)) ^ lx;
            #pragma unroll
            for (int mt = 0; mt < 4; mt++)
                ldmx4(af[pb][mt], stA + ((uint32_t)(wm + mt * 16 + arow) << 7) + koffA);
            #pragma unroll
            for (int j = 0; j < 4; j++)
                ldmx4(bf[pb][j], stB + ((uint32_t)(wn + j * 16 + brow) << 7) + koffB);
        };

        load_frags(0, 0);
        #pragma unroll
        for (int ks = 0; ks < 4; ks++) {
            const int cur = ks & 1;
            if (pf) load_quarter(c + 2, ps, ks);          // spread producer issues
            if (ks < 3) load_frags(ks + 1, cur ^ 1);
            #pragma unroll
            for (int mt = 0; mt < 4; mt++)
                #pragma unroll
                for (int nt = 0; nt < 8; nt++)
                    mma16816(&acc[(mt * 8 + nt) * 4], af[cur][mt],
                             bf[cur][nt >> 1][(nt & 1) * 2], bf[cur][nt >> 1][(nt & 1) * 2 + 1]);
        }
        if (pf) cpcommit();
    }
    __syncthreads();   // retire last-stage reads before smem reuse

    // ------------- epilogue -------------
    const int cl = (l & 3) << 1;

    if (MODE == 0 && n0 >= 1024) {
        // KV tile: warp's 64 cols = [32 K-ch | 32 matching V-ch]; pair nt <-> nt+4
        const int hbase = ((n0 - 1024) >> 6) * 32;
        const int hw = hbase + (wn >> 1);
        const int bn = (int)(m0 / SEQ);
        float pkv[8], pks[8];
        #pragma unroll
        for (int i = 0; i < 8; i++) { pkv[i] = 0.f; pks[i] = 0.f; }
        #pragma unroll
        for (int mt = 0; mt < 4; mt++)
            #pragma unroll
            for (int nt = 0; nt < 4; nt++)
                #pragma unroll
                for (int i = 0; i < 4; i++) {
                    int hl = nt * 8 + cl + (i & 1);
                    float kf = elu1(acc[(mt * 8 + nt) * 4 + i] + __ldg(&b1p[hw + hl]));
                    float vv = acc[(mt * 8 + nt + 4) * 4 + i] + __ldg(&b2p[hw + hl]);
                    int e = nt * 2 + (i & 1);
                    pkv[e] += kf * vv;
                    pks[e] += kf;
                }
        #pragma unroll
        for (int off = 16; off >= 4; off >>= 1)
            #pragma unroll
            for (int e = 0; e < 8; e++) {
                pkv[e] += __shfl_down_sync(0xffffffffu, pkv[e], off);
                pks[e] += __shfl_down_sync(0xffffffffu, pks[e], off);
            }
        float* redkv = (float*)smv;          // [4 warps][32]
        float* redks = redkv + 4 * 32;
        if (l < 4) {
            #pragma unroll
            for (int e = 0; e < 8; e++) {
                int hl = (e >> 1) * 8 + l * 2 + (e & 1);
                redkv[w * 32 + hl] = pkv[e];
                redks[w * 32 + hl] = pks[e];
            }
        }
        __syncthreads();
        {
            int cc = tid & 63;
            int w0 = (cc >> 5) * 2;          // warps {0,1} cols 0-63; {2,3} cols 64-127
            float* src = (tid < 64) ? redkv : redks;
            float s = src[w0 * 32 + (cc & 31)] + src[(w0 + 1) * 32 + (cc & 31)];
            float* dst = (tid < 64) ? &g_KV[bn * H + hbase + cc]
                                    : &g_Ksum[bn * H + hbase + cc];
            atomicAdd(dst, s);
        }
    } else {
        // Q tile (MODE 0, elu1 -> g_Qf fp16) or out tile (MODE 1, gelu -> fp32)
        float* ep = (float*)smv;             // [128][132]
        #pragma unroll
        for (int mt = 0; mt < 4; mt++)
            #pragma unroll
            for (int nt = 0; nt < 8; nt++) {
                int c0 = wn + nt * 8 + cl;
                float bb0 = __ldg(&b0p[n0 + c0]);
                float bb1 = __ldg(&b0p[n0 + c0 + 1]);
                int r0 = wm + mt * 16 + (l >> 2);
                float v0 = acc[(mt * 8 + nt) * 4 + 0] + bb0;
                float v1 = acc[(mt * 8 + nt) * 4 + 1] + bb1;
                float v2 = acc[(mt * 8 + nt) * 4 + 2] + bb0;
                float v3 = acc[(mt * 8 + nt) * 4 + 3] + bb1;
                if (MODE == 0) { v0 = elu1(v0); v1 = elu1(v1); v2 = elu1(v2); v3 = elu1(v3); }
                else           { v0 = gelu(v0); v1 = gelu(v1); v2 = gelu(v2); v3 = gelu(v3); }
                ep[r0 * 132 + c0] = v0;        ep[r0 * 132 + c0 + 1] = v1;
                ep[(r0 + 8) * 132 + c0] = v2;  ep[(r0 + 8) * 132 + c0 + 1] = v3;
            }
        __syncthreads();
        if (MODE == 0) {
            #pragma unroll 8
            for (int i = 0; i < 128; i++) {
                int idx = i * 128 + tid;
                int rr = idx >> 7, cc = idx & 127;
                g_Qf[(m0 + rr) * H + n0 + cc] = __float2half(ep[rr * 132 + cc]);
            }
        } else {
            #pragma unroll 8
            for (int i = 0; i < 128; i++) {
                int idx = i * 128 + tid;
                int rr = idx >> 7, cc = idx & 127;
                outp[(m0 + rr) * H + n0 + cc] = ep[rr * 132 + cc];
            }
        }
    }
}

// ---------------- launch --------------------------------------------------
extern "C" void kernel_launch(void* const* d_in, const int* in_sizes, int n_in,
                              void* d_out, int out_size) {
    const float* x  = (const float*)d_in[0];
    const float* wq = (const float*)d_in[1];
    const float* bq = (const float*)d_in[2];
    const float* wk = (const float*)d_in[3];
    const float* bk = (const float*)d_in[4];
    const float* wv = (const float*)d_in[5];
    const float* bv = (const float*)d_in[6];
    const float* wo = (const float*)d_in[7];
    const float* bo = (const float*)d_in[8];
    float* out = (float*)d_out;

    cudaFuncSetAttribute(gemm_kernel<0>, cudaFuncAttributeMaxDynamicSharedMemorySize, SMEM_TOTAL);
    cudaFuncSetAttribute(gemm_kernel<1>, cudaFuncAttributeMaxDynamicSharedMemorySize, SMEM_TOTAL);

    conv_x_kernel<<<M_TOTAL * H / 1024, 256>>>(x);
    conv_w_kernel<<<dim3(256, 4), 256>>>(wq, wk, wv, wo);

    gemm_kernel<0><<<dim3(24, M_TOTAL / 128), 128, SMEM_TOTAL>>>(bq, bk, bv, nullptr);
    vprime_kernel<<<M_TOTAL, 256>>>();
    gemm_kernel<1><<<dim3(8, M_TOTAL / 128), 128, SMEM_TOTAL>>>(bo, nullptr, nullptr, out);
}